// round 1
// baseline (speedup 1.0000x reference)
#include <cuda_runtime.h>
#include <cstdint>

#define L 4096
#define NB 4

// Scratch (no device allocation allowed in kernel_launch)
__device__ int   g_seq[L];
__device__ float g_rows[NB * L];   // g_rows[c][x] = base_table[seq[x]*4 + c], c in 0..3

// ---------------------------------------------------------------------------
// Prep: detect int32 vs int64 seq_ids, decode, and build the 4 value rows.
// One block, 1024 threads.
// ---------------------------------------------------------------------------
__global__ void prep_kernel(const void* __restrict__ seq_raw,
                            const float* __restrict__ base_table) {
    __shared__ int s_nonzero_odd;   // any nonzero odd 32-bit word in first 4096 words?
    const int tid = threadIdx.x;
    const int* w = (const int*)seq_raw;

    if (tid == 0) s_nonzero_odd = 0;
    __syncthreads();

    // If seq_ids is int64 (values 0..3, little-endian), words [1,3,5,...,4095]
    // are the high halves of elements 0..2047 -> all zero.
    // If seq_ids is int32, those words are random in 0..3 -> virtually
    // certainly at least one nonzero among 2048 samples.
    // All reads stay within the smaller (int32) buffer size of 16 KB.
    int local = 0;
    for (int k = tid; k < 2048; k += blockDim.x) {
        if (w[2 * k + 1] != 0) local = 1;
    }
    if (local) atomicOr(&s_nonzero_odd, 1);
    __syncthreads();

    const bool is64 = (s_nonzero_odd == 0);

    // Load base_table into registers-ish (16 floats, tiny)
    for (int i = tid; i < L; i += blockDim.x) {
        int s = is64 ? w[2 * i] : w[i];
        g_seq[i] = s;
        #pragma unroll
        for (int c = 0; c < NB; c++) {
            g_rows[c * L + i] = base_table[s * NB + c];
        }
    }
}

// ---------------------------------------------------------------------------
// Fill: 8*4096 rows of 4096 fp32. One block per row, 1024 threads, one
// float4 (STG.128) per thread. Pure store streaming.
//   c in [0,4): value constant along the row: g_rows[c][i]
//   c in [4,8): row == g_rows[c-4][0..4095], identical for every i
// ---------------------------------------------------------------------------
__global__ void __launch_bounds__(1024, 2)
fill_kernel(float4* __restrict__ out) {
    const unsigned row = blockIdx.x;        // 0 .. 8*4096-1
    const int c = row >> 12;                // channel 0..7
    const int i = row & 4095;               // row within channel
    const int tid = threadIdx.x;            // 0..1023

    float4 v;
    if (c < 4) {
        const float s = g_rows[(c << 12) + i];
        v = make_float4(s, s, s, s);
    } else {
        const float4* r = (const float4*)&g_rows[(c & 3) << 12];
        v = r[tid];                         // L2-resident 16 KB row
    }
    out[(size_t)row * 1024 + tid] = v;
}

extern "C" void kernel_launch(void* const* d_in, const int* in_sizes, int n_in,
                              void* d_out, int out_size) {
    const void*  seq        = d_in[0];
    const float* base_table = (const float*)d_in[1];
    float4* out = (float4*)d_out;

    prep_kernel<<<1, 1024>>>(seq, base_table);
    fill_kernel<<<8 * L, 1024>>>(out);
}

// round 2
// speedup vs baseline: 1.1572x; 1.1572x over previous
#include <cuda_runtime.h>
#include <cstdint>

#define L 4096
#define NB 4

// Scratch (no device allocation allowed in kernel_launch)
__device__ float g_rows[NB * L];   // g_rows[c*L + x] = base_table[seq[x]*4 + c]

// ---------------------------------------------------------------------------
// Prep: detect int32 vs int64 seq_ids, decode, build the 4 value rows.
// One block, 1024 threads.
// ---------------------------------------------------------------------------
__global__ void prep_kernel(const void* __restrict__ seq_raw,
                            const float* __restrict__ base_table) {
    __shared__ int s_nonzero_odd;
    const int tid = threadIdx.x;
    const int* w = (const int*)seq_raw;

    if (tid == 0) s_nonzero_odd = 0;
    __syncthreads();

    // int64 seq (values 0..3): odd 32-bit words of the first 2048 elements are 0.
    // int32 seq: those words are random base ids -> ~certainly nonzero somewhere.
    int local = 0;
    for (int k = tid; k < 2048; k += blockDim.x) {
        if (w[2 * k + 1] != 0) local = 1;
    }
    if (local) atomicOr(&s_nonzero_odd, 1);
    __syncthreads();

    const bool is64 = (s_nonzero_odd == 0);

    for (int i = tid; i < L; i += blockDim.x) {
        const int s = is64 ? w[2 * i] : w[i];
        #pragma unroll
        for (int c = 0; c < NB; c++) {
            g_rows[c * L + i] = base_table[s * NB + c];
        }
    }
}

// ---------------------------------------------------------------------------
// Fill: 2048 blocks x 256 threads, 64 x STG.128 per thread (1 KB/thread).
//
// Blocks [0,1024): channels 4..7 (value depends on column only).
//   block -> (c2 = channel-4, chunk of 256 float4 columns, slice of 64 rows).
//   Each thread registers its column value ONCE, then streams 64 stores
//   down the rows (stride 16 KB). No loads in the inner loop.
//
// Blocks [1024,2048): channels 0..3 (value depends on row only).
//   block -> 16 consecutive rows; per row: one broadcast scalar load,
//   4 broadcast float4 stores per thread (full 16 KB row per block-row).
//   Global row id == index into g_rows directly (row = c*4096 + i).
// ---------------------------------------------------------------------------
__global__ void __launch_bounds__(256, 8)
fill_kernel(float4* __restrict__ out) {
    const int tid = threadIdx.x;
    const unsigned b = blockIdx.x;

    if (b < 1024u) {
        const int c2    = b >> 8;          // 0..3  (channel - 4)
        const int sub   = b & 255;
        const int chunk = sub & 3;         // 0..3 : which 256-float4 column chunk
        const int slice = sub >> 2;        // 0..63: which 64-row slice

        const float4 v = ((const float4*)&g_rows[c2 << 12])[(chunk << 8) + tid];

        float4* p = out
                  + (((size_t)(4 + c2) << 12) + ((size_t)slice << 6)) * 1024
                  + (chunk << 8) + tid;
        #pragma unroll 8
        for (int i = 0; i < 64; i++) {
            p[0] = v;
            p += 1024;                     // next row, same column
        }
    } else {
        const unsigned row0 = (b - 1024u) << 4;   // 16 rows, global rows 0..16383
        #pragma unroll 1
        for (int r = 0; r < 16; r++) {
            const unsigned row = row0 + r;
            const float s = g_rows[row];          // row == c*4096 + i
            const float4 v = make_float4(s, s, s, s);
            float4* o = out + (size_t)row * 1024 + tid;
            #pragma unroll
            for (int k = 0; k < 4; k++)
                o[k * 256] = v;
        }
    }
}

extern "C" void kernel_launch(void* const* d_in, const int* in_sizes, int n_in,
                              void* d_out, int out_size) {
    const void*  seq        = d_in[0];
    const float* base_table = (const float*)d_in[1];

    prep_kernel<<<1, 1024>>>(seq, base_table);
    fill_kernel<<<2048, 256>>>((float4*)d_out);
}